// round 1
// baseline (speedup 1.0000x reference)
#include <cuda_runtime.h>
#include <cuda_bf16.h>

// Problem shape (fixed): pred/target (B=4, C=2, T=8, H=512, W=512) f32
// out = mean( (box9(pred) - box9(target))^2 )  with zero padding on H,W.
// Simplifications:
//   box9(pred)-box9(target) = box9(pred-target)   (linearity)
//   box9 = 9-wide horizontal sum o 9-tall vertical sum, scaled by 1/81.

#define W 512
#define H 512
#define NIMG 64                   // B*C*T = 4*2*8
#define NTOT (16777216.0)         // B*C*T*H*W
#define POOLK 9
#define HALO 4

#define TW 128
#define TH 32
#define IW (TW + 2*HALO)          // 136
#define IH (TH + 2*HALO)          // 40

__device__ double g_sum;

__global__ void zero_kernel() { g_sum = 0.0; }

__global__ void finalize_kernel(float* out) {
    // divide by 81^2 (box normalization, applied once) and by N for the mean
    out[0] = (float)(g_sum / (81.0 * 81.0) / NTOT);
}

__global__ __launch_bounds__(256)
void pooled_mse_kernel(const float* __restrict__ pred,
                       const float* __restrict__ target) {
    __shared__ float s_in[IH][IW];    // diff tile with halo
    __shared__ float s_h[IH][TW];     // horizontal 9-sums
    __shared__ float s_red[8];

    const int tid  = threadIdx.x;
    const int img  = blockIdx.z;
    const int x0   = blockIdx.x * TW;   // tile origin (output coords)
    const int y0   = blockIdx.y * TH;
    const long base = (long)img * (H * W);

    // ---- load diff tile (with zero-padded halo) ----
    #pragma unroll
    for (int i = tid; i < IH * IW; i += 256) {
        const int ly = i / IW;
        const int lx = i - ly * IW;
        const int gx = x0 + lx - HALO;
        const int gy = y0 + ly - HALO;
        float v = 0.0f;
        if ((unsigned)gx < (unsigned)W && (unsigned)gy < (unsigned)H) {
            const long idx = base + (long)gy * W + gx;
            v = pred[idx] - target[idx];
        }
        s_in[ly][lx] = v;
    }
    __syncthreads();

    // ---- horizontal 9-sum: s_h[r][c] = sum_{k=0..8} s_in[r][c+k] ----
    #pragma unroll
    for (int i = tid; i < IH * TW; i += 256) {
        const int r = i / TW;
        const int c = i - r * TW;
        float s = 0.0f;
        #pragma unroll
        for (int k = 0; k < POOLK; k++) s += s_in[r][c + k];
        s_h[r][c] = s;
    }
    __syncthreads();

    // ---- vertical 9-sum + square-accumulate ----
    float acc = 0.0f;
    #pragma unroll
    for (int i = tid; i < TH * TW; i += 256) {
        const int r = i / TW;     // output row in tile
        const int c = i - r * TW;
        float s = 0.0f;
        #pragma unroll
        for (int k = 0; k < POOLK; k++) s += s_h[r + k][c];
        acc += s * s;             // scale by 1/81^2 applied in finalize
    }

    // ---- block reduction ----
    #pragma unroll
    for (int off = 16; off > 0; off >>= 1)
        acc += __shfl_xor_sync(0xFFFFFFFFu, acc, off);
    const int warp = tid >> 5;
    const int lane = tid & 31;
    if (lane == 0) s_red[warp] = acc;
    __syncthreads();
    if (warp == 0) {
        float v = (lane < 8) ? s_red[lane] : 0.0f;
        #pragma unroll
        for (int off = 4; off > 0; off >>= 1)
            v += __shfl_xor_sync(0xFFFFFFFFu, v, off);
        if (lane == 0) atomicAdd(&g_sum, (double)v);
    }
}

extern "C" void kernel_launch(void* const* d_in, const int* in_sizes, int n_in,
                              void* d_out, int out_size) {
    const float* pred   = (const float*)d_in[0];
    const float* target = (const float*)d_in[1];
    float* out = (float*)d_out;

    zero_kernel<<<1, 1>>>();
    dim3 grid(W / TW, H / TH, NIMG);   // 4 x 16 x 64 = 4096 blocks
    pooled_mse_kernel<<<grid, 256>>>(pred, target);
    finalize_kernel<<<1, 1>>>(out);
}

// round 2
// speedup vs baseline: 1.9437x; 1.9437x over previous
#include <cuda_runtime.h>
#include <cuda_bf16.h>

// out = mean( (box9(pred) - box9(target))^2 ), zero-padded on H,W.
// box9(pred)-box9(target) = box9(pred-target); box9 separable into 9-wide
// horizontal sum then 9-tall vertical sum; normalize by 81^2 at the end.
//
// Layout: pred/target (4,2,8,512,512) f32 -> 64 images of 512x512.
// One block = full-width (512) x 64 output rows. Grid = 64*8 = 512 blocks.
// Pipeline per batch of 8 input rows:
//   load diff rows -> smem  (float4, coalesced)
//   horizontal 9-sums in registers (3x LDS.128 -> 4 hsums), STS to 16-row ring
//   vertical 9-sum via sliding window over the ring (registers), square+acc

#define Wd   512
#define Hd   512
#define NIMG 64
#define TH   64
#define NBLK (NIMG * (Hd / TH))   // 512
#define RS   512                  // smem row stride (floats)
#define RING 16
#define NTOT 16777216.0           // 4*2*8*512*512

__device__ double        g_sum  = 0.0;
__device__ unsigned int  g_done = 0;

__global__ __launch_bounds__(256)
void pooled_mse_kernel(const float* __restrict__ pred,
                       const float* __restrict__ target,
                       float* __restrict__ out) {
    __shared__ float s_d[8 * RS];      // 16 KB: diff rows of current batch
    __shared__ float s_h[RING * RS];   // 32 KB: hsum ring (16 rows)

    const int tid   = threadIdx.x;
    const int img   = blockIdx.x >> 3;      // 8 strips per image
    const int strip = blockIdx.x & 7;
    const int y0    = strip * TH;

    const size_t ibase = (size_t)img * (Hd * Wd);
    const float* pbase = pred + ibase;
    const float* tbase = target + ibase;

    float acc = 0.0f;

    #pragma unroll 1
    for (int b = 0; b < 9; b++) {
        // ---- load batch b: input rows (y0-4+8b) .. +7, as diff, zero-padded in y
        #pragma unroll
        for (int k = 0; k < 4; k++) {
            const int j   = tid + k * 256;        // float4 task id, 0..1023
            const int row = j >> 7;               // 0..7
            const int xq  = (j & 127) << 2;       // 0..508
            const int r   = y0 - 4 + b * 8 + row; // absolute input row
            float4 v = make_float4(0.f, 0.f, 0.f, 0.f);
            if ((unsigned)r < (unsigned)Hd) {
                const float4 p4 = *(const float4*)(pbase + (size_t)r * Wd + xq);
                const float4 t4 = *(const float4*)(tbase + (size_t)r * Wd + xq);
                v = make_float4(p4.x - t4.x, p4.y - t4.y, p4.z - t4.z, p4.w - t4.w);
            }
            *(float4*)(s_d + row * RS + xq) = v;
        }
        __syncthreads();

        // ---- horizontal 9-sums: thread (cg, rr) -> cols 4cg..4cg+3, rows rr+2k
        {
            const int cg = tid & 127;
            const int rr = tid >> 7;
            const int x0 = cg << 2;
            #pragma unroll
            for (int k = 0; k < 4; k++) {
                const int row = rr + k * 2;
                const float* drow = s_d + row * RS;
                float4 a = (cg == 0)   ? make_float4(0.f,0.f,0.f,0.f)
                                       : *(const float4*)(drow + x0 - 4);
                float4 m = *(const float4*)(drow + x0);
                float4 c = (cg == 127) ? make_float4(0.f,0.f,0.f,0.f)
                                       : *(const float4*)(drow + x0 + 4);
                const float h0 = ((a.x + a.y) + (a.z + a.w))
                               + ((m.x + m.y) + (m.z + m.w)) + c.x;
                const float h1 = h0 - a.x + c.y;
                const float h2 = h1 - a.y + c.z;
                const float h3 = h2 - a.z + c.w;
                const int ridx = (b * 8 + row) & (RING - 1);
                *(float4*)(s_h + ridx * RS + x0) = make_float4(h0, h1, h2, h3);
            }
        }
        __syncthreads();

        // ---- vertical sliding 9-sum for output rows of group (b-1)
        // ring index of absolute input row r is (r - (y0-4)) & 15
        if (b >= 1) {
            const int c0    = tid << 1;        // 2 columns per thread
            const int ysrel = 8 * (b - 1);     // output rows y0+ysrel .. +7
            float2 vs = make_float2(0.f, 0.f);
            #pragma unroll
            for (int k = 0; k < 9; k++) {      // init: rows rel ysrel..ysrel+8
                const int ridx = (ysrel + k) & (RING - 1);
                const float2 h = *(const float2*)(s_h + ridx * RS + c0);
                vs.x += h.x; vs.y += h.y;
            }
            acc += vs.x * vs.x + vs.y * vs.y;
            #pragma unroll
            for (int k = 1; k < 8; k++) {      // slide
                const int iadd = (ysrel + k + 8) & (RING - 1);
                const int isub = (ysrel + k - 1) & (RING - 1);
                const float2 ha = *(const float2*)(s_h + iadd * RS + c0);
                const float2 hb = *(const float2*)(s_h + isub * RS + c0);
                vs.x += ha.x - hb.x; vs.y += ha.y - hb.y;
                acc += vs.x * vs.x + vs.y * vs.y;
            }
        }
    }

    // ---- block reduction (reuse s_d as scratch) ----
    __syncthreads();
    #pragma unroll
    for (int off = 16; off > 0; off >>= 1)
        acc += __shfl_xor_sync(0xFFFFFFFFu, acc, off);
    float* s_red = s_d;
    const int warp = tid >> 5;
    const int lane = tid & 31;
    if (lane == 0) s_red[warp] = acc;
    __syncthreads();
    if (warp == 0) {
        float v = (lane < 8) ? s_red[lane] : 0.0f;
        #pragma unroll
        for (int off = 4; off > 0; off >>= 1)
            v += __shfl_xor_sync(0xFFFFFFFFu, v, off);
        if (lane == 0) {
            atomicAdd(&g_sum, (double)v);
            __threadfence();
            const unsigned old = atomicAdd(&g_done, 1u);
            if (old == NBLK - 1) {
                const double s = *((volatile double*)&g_sum);
                out[0] = (float)(s / (81.0 * 81.0) / NTOT);
                g_sum  = 0.0;     // reset for next graph replay
                g_done = 0u;
            }
        }
    }
}

extern "C" void kernel_launch(void* const* d_in, const int* in_sizes, int n_in,
                              void* d_out, int out_size) {
    const float* pred   = (const float*)d_in[0];
    const float* target = (const float*)d_in[1];
    float* out = (float*)d_out;
    pooled_mse_kernel<<<NBLK, 256>>>(pred, target, out);
}